// round 3
// baseline (speedup 1.0000x reference)
#include <cuda_runtime.h>
#include <math.h>

// Problem constants
#define BATCH 4
#define DMODEL 1024
#define SEQ 2048
#define NHEAD 16
#define HDIM 64
#define NTOK (BATCH * SEQ)   // 8192

// -------------------- scratch (device globals; no allocation) --------------------
__device__ float g_freq[DMODEL / 2];                       // PE frequencies
__device__ float g_xe[(size_t)NTOK * DMODEL];              // x + PE, [b,s,d]  (32 MB)
__device__ float g_q[(size_t)NTOK * DMODEL];               // [b,h,s,hd]       (32 MB)
__device__ float g_k[(size_t)NTOK * DMODEL];               // [b,h,s,hd]       (32 MB)
__device__ float g_v[(size_t)NTOK * DMODEL];               // [b,h,s,hd]       (32 MB)
__device__ float g_ao[(size_t)NTOK * DMODEL];              // attn out, [b,s,d](32 MB)

// -------------------- PE frequency init (double exp, 512 elems, trivial) --------
__global__ void k_init_freq() {
    int i = threadIdx.x;
    if (i < DMODEL / 2) {
        // denom = exp(-(2i) * ln(10000)/D), correctly rounded to fp32
        g_freq[i] = (float)exp(-(double)(2 * i) * (9.210340371976184 / 1024.0));
    }
}

// -------------------- x + PE, transpose [B,D,S] -> [B,S,D] -----------------------
__global__ void k_pe_transpose(const float* __restrict__ x) {
    __shared__ float tile[32][33];
    int b  = blockIdx.z;
    int d0 = blockIdx.y * 32;
    int s0 = blockIdx.x * 32;
    int txx = threadIdx.x, tyy = threadIdx.y;
    const float* xb = x + (size_t)b * DMODEL * SEQ;
#pragma unroll
    for (int r = 0; r < 4; r++) {
        int d = d0 + tyy + r * 8;
        int s = s0 + txx;
        float freq = g_freq[d >> 1];
        float ang  = (float)s * freq;              // fp32 mul, matches JAX pipeline
        float pe   = (d & 1) ? cosf(ang) : sinf(ang);
        tile[tyy + r * 8][txx] = xb[(size_t)d * SEQ + s] + pe;
    }
    __syncthreads();
#pragma unroll
    for (int r = 0; r < 4; r++) {
        int sl = tyy + r * 8;
        g_xe[((size_t)b * SEQ + s0 + sl) * DMODEL + d0 + txx] = tile[txx][sl];
    }
}

// -------------------- SGEMM mainloop (128x128x8, 8x8/thread) --------------------
// Computes acc[8][8] for C[m0+ty*8+i][n0+tx*8+j] = sum_k A[m][k] * W[n][k]
#define GEMM_MAINLOOP(APTR, WPTR)                                              \
    __shared__ float As[8][128];                                               \
    __shared__ float Bs[8][128];                                               \
    int tid = threadIdx.x;                                                     \
    int tx = tid & 15, ty = tid >> 4;                                          \
    int n0 = blockIdx.x * 128, m0 = blockIdx.y * 128;                          \
    int lr = tid >> 1;                                                         \
    int lc = (tid & 1) * 4;                                                    \
    const float* ap = (APTR) + (size_t)(m0 + lr) * DMODEL + lc;                \
    const float* wp = (WPTR) + (size_t)(n0 + lr) * DMODEL + lc;                \
    float acc[8][8];                                                           \
    _Pragma("unroll") for (int i = 0; i < 8; i++)                              \
        _Pragma("unroll") for (int j = 0; j < 8; j++) acc[i][j] = 0.0f;        \
    float4 av = *(const float4*)ap;                                            \
    float4 wv = *(const float4*)wp;                                            \
    for (int k0 = 0; k0 < DMODEL; k0 += 8) {                                   \
        __syncthreads();                                                       \
        As[lc + 0][lr] = av.x; As[lc + 1][lr] = av.y;                          \
        As[lc + 2][lr] = av.z; As[lc + 3][lr] = av.w;                          \
        Bs[lc + 0][lr] = wv.x; Bs[lc + 1][lr] = wv.y;                          \
        Bs[lc + 2][lr] = wv.z; Bs[lc + 3][lr] = wv.w;                          \
        __syncthreads();                                                       \
        if (k0 + 8 < DMODEL) {                                                 \
            av = *(const float4*)(ap + k0 + 8);                                \
            wv = *(const float4*)(wp + k0 + 8);                                \
        }                                                                      \
        _Pragma("unroll") for (int kk = 0; kk < 8; kk++) {                     \
            float ar[8], br[8];                                                \
            *(float4*)&ar[0] = *(const float4*)&As[kk][ty * 8];                \
            *(float4*)&ar[4] = *(const float4*)&As[kk][ty * 8 + 4];            \
            *(float4*)&br[0] = *(const float4*)&Bs[kk][tx * 8];                \
            *(float4*)&br[4] = *(const float4*)&Bs[kk][tx * 8 + 4];            \
            _Pragma("unroll") for (int i = 0; i < 8; i++)                      \
                _Pragma("unroll") for (int j = 0; j < 8; j++)                  \
                    acc[i][j] += ar[i] * br[j];                                \
        }                                                                      \
    }

// QKV projection: A = g_xe [NTOK, D]; out scattered to [b,h,s,hd]
__global__ __launch_bounds__(256) void k_gemm_qkv(const float* __restrict__ W,
                                                  const float* __restrict__ bias,
                                                  int which) {
    float* out = (which == 0) ? g_q : (which == 1) ? g_k : g_v;
    GEMM_MAINLOOP(g_xe, W)
#pragma unroll
    for (int i = 0; i < 8; i++) {
        int row = m0 + ty * 8 + i;
        int bb = row >> 11;            // / SEQ
        int s  = row & (SEQ - 1);
#pragma unroll
        for (int j4 = 0; j4 < 8; j4 += 4) {
            int jg = n0 + tx * 8 + j4;
            int h  = jg >> 6;
            int hd = jg & 63;
            float4 o;
            o.x = acc[i][j4 + 0] + bias[jg + 0];
            o.y = acc[i][j4 + 1] + bias[jg + 1];
            o.z = acc[i][j4 + 2] + bias[jg + 2];
            o.w = acc[i][j4 + 3] + bias[jg + 3];
            *(float4*)&out[(((size_t)(bb * NHEAD + h) * SEQ + s) * HDIM) + hd] = o;
        }
    }
}

// Output projection: A = g_ao [NTOK, D]; out transposed to [B, D, S]
__global__ __launch_bounds__(256) void k_gemm_out(const float* __restrict__ W,
                                                  const float* __restrict__ bias,
                                                  float* __restrict__ out) {
    GEMM_MAINLOOP(g_ao, W)
#pragma unroll
    for (int j = 0; j < 8; j++) {
        int jg = n0 + tx * 8 + j;
        float bv = bias[jg];
#pragma unroll
        for (int i4 = 0; i4 < 8; i4 += 4) {
            int row = m0 + ty * 8 + i4;
            int bb = row >> 11;
            int s  = row & (SEQ - 1);
            float4 o;
            o.x = acc[i4 + 0][j] + bv;
            o.y = acc[i4 + 1][j] + bv;
            o.z = acc[i4 + 2][j] + bv;
            o.w = acc[i4 + 3][j] + bv;
            *(float4*)&out[((size_t)bb * DMODEL + jg) * SEQ + s] = o;
        }
    }
}

// -------------------- flash attention (fp32, Br=Bc=64) ---------------------------
// grid: (SEQ/64, B*H), block 256 (16x16 logical). Smem: Qt 16K + K/P union 16K + V 16K = 48K.
__global__ __launch_bounds__(256) void k_flash() {
    __shared__ float Qt[64 * 64];   // [k][r]  (transposed Q, pre-scaled by 0.125)
    __shared__ float KP[64 * 64];   // K as [k][c]; reused as P as [c][r]
    __shared__ float Vs[64 * 64];   // [kc][c]

    int tid = threadIdx.x;
    int tx = tid & 15, ty = tid >> 4;
    int bh = blockIdx.y;
    int q0 = blockIdx.x * 64;
    const float* qp = g_q + ((size_t)bh * SEQ + q0) * HDIM;
    const float* kp = g_k + (size_t)bh * SEQ * HDIM;
    const float* vp = g_v + (size_t)bh * SEQ * HDIM;

    // Load Q tile transposed, scale by 1/sqrt(hd) = 0.125 (exact)
    {
        int r  = tid >> 2;
        int c0 = (tid & 3) * 16;
#pragma unroll
        for (int u = 0; u < 4; u++) {
            float4 v = *(const float4*)(qp + (size_t)r * HDIM + c0 + u * 4);
            Qt[(c0 + u * 4 + 0) * 64 + r] = v.x * 0.125f;
            Qt[(c0 + u * 4 + 1) * 64 + r] = v.y * 0.125f;
            Qt[(c0 + u * 4 + 2) * 64 + r] = v.z * 0.125f;
            Qt[(c0 + u * 4 + 3) * 64 + r] = v.w * 0.125f;
        }
    }

    float m_i[4], l_i[4], acc[16];
#pragma unroll
    for (int i = 0; i < 4; i++) { m_i[i] = -1e30f; l_i[i] = 0.0f; }
#pragma unroll
    for (int i = 0; i < 16; i++) acc[i] = 0.0f;

    for (int kt = 0; kt < SEQ / 64; kt++) {
        const float* kb = kp + (size_t)kt * 64 * HDIM;
        const float* vb = vp + (size_t)kt * 64 * HDIM;
        // Load K transposed into KP
        {
            int r  = tid >> 2;
            int c0 = (tid & 3) * 16;
#pragma unroll
            for (int u = 0; u < 4; u++) {
                float4 v = *(const float4*)(kb + (size_t)r * HDIM + c0 + u * 4);
                KP[(c0 + u * 4 + 0) * 64 + r] = v.x;
                KP[(c0 + u * 4 + 1) * 64 + r] = v.y;
                KP[(c0 + u * 4 + 2) * 64 + r] = v.z;
                KP[(c0 + u * 4 + 3) * 64 + r] = v.w;
            }
        }
        // Load V flat (layout matches)
#pragma unroll
        for (int u = 0; u < 4; u++) {
            float4 v = *(const float4*)(vb + (size_t)(u * 256 + tid) * 4);
            *(float4*)&Vs[(u * 256 + tid) * 4] = v;
        }
        __syncthreads();

        // S = Q K^T  (scaled): s[i][j] for rows ty*4+i, cols tx*4+j
        float sv[16];
#pragma unroll
        for (int i = 0; i < 16; i++) sv[i] = 0.0f;
#pragma unroll 16
        for (int k = 0; k < 64; k++) {
            float4 a = *(const float4*)&Qt[k * 64 + ty * 4];
            float4 b = *(const float4*)&KP[k * 64 + tx * 4];
            float ar[4] = {a.x, a.y, a.z, a.w};
            float br[4] = {b.x, b.y, b.z, b.w};
#pragma unroll
            for (int i = 0; i < 4; i++)
#pragma unroll
                for (int j = 0; j < 4; j++) sv[i * 4 + j] += ar[i] * br[j];
        }

        // Online softmax update (row groups = 16 lanes within each warp half)
#pragma unroll
        for (int i = 0; i < 4; i++) {
            float rm = fmaxf(fmaxf(sv[i * 4 + 0], sv[i * 4 + 1]),
                             fmaxf(sv[i * 4 + 2], sv[i * 4 + 3]));
#pragma unroll
            for (int off = 1; off < 16; off <<= 1)
                rm = fmaxf(rm, __shfl_xor_sync(0xffffffffu, rm, off));
            float mn = fmaxf(m_i[i], rm);
            float alpha = __expf(m_i[i] - mn);
            m_i[i] = mn;
            float rs = 0.0f;
#pragma unroll
            for (int j = 0; j < 4; j++) {
                sv[i * 4 + j] = __expf(sv[i * 4 + j] - mn);
                rs += sv[i * 4 + j];
            }
#pragma unroll
            for (int off = 1; off < 16; off <<= 1)
                rs += __shfl_xor_sync(0xffffffffu, rs, off);
            l_i[i] = l_i[i] * alpha + rs;
#pragma unroll
            for (int j = 0; j < 4; j++) acc[i * 4 + j] *= alpha;
        }
        __syncthreads();   // all reads of KP (as K) done

        // Write P transposed into KP: KP[c][r]
#pragma unroll
        for (int j = 0; j < 4; j++) {
            float4 pv = make_float4(sv[0 * 4 + j], sv[1 * 4 + j],
                                    sv[2 * 4 + j], sv[3 * 4 + j]);
            *(float4*)&KP[(tx * 4 + j) * 64 + ty * 4] = pv;
        }
        __syncthreads();

        // O += P V
#pragma unroll 16
        for (int kc = 0; kc < 64; kc++) {
            float4 a = *(const float4*)&KP[kc * 64 + ty * 4];
            float4 b = *(const float4*)&Vs[kc * 64 + tx * 4];
            float ar[4] = {a.x, a.y, a.z, a.w};
            float br[4] = {b.x, b.y, b.z, b.w};
#pragma unroll
            for (int i = 0; i < 4; i++)
#pragma unroll
                for (int j = 0; j < 4; j++) acc[i * 4 + j] += ar[i] * br[j];
        }
        __syncthreads();   // before next tile's loads overwrite KP/Vs
    }

    // Normalize and write to g_ao in [b, s, d] layout
    int bb = bh >> 4;         // / NHEAD
    int h  = bh & 15;
#pragma unroll
    for (int i = 0; i < 4; i++) {
        float inv = 1.0f / l_i[i];
        int row = q0 + ty * 4 + i;
        float4 o;
        o.x = acc[i * 4 + 0] * inv;
        o.y = acc[i * 4 + 1] * inv;
        o.z = acc[i * 4 + 2] * inv;
        o.w = acc[i * 4 + 3] * inv;
        *(float4*)&g_ao[((size_t)(bb * SEQ + row)) * DMODEL + h * HDIM + tx * 4] = o;
    }
}

// -------------------- launch --------------------------------------------------
extern "C" void kernel_launch(void* const* d_in, const int* in_sizes, int n_in,
                              void* d_out, int out_size) {
    (void)in_sizes; (void)n_in; (void)out_size;
    const float* x  = (const float*)d_in[0];
    const float* Wq = (const float*)d_in[1];
    const float* bq = (const float*)d_in[2];
    const float* Wk = (const float*)d_in[3];
    const float* bk = (const float*)d_in[4];
    const float* Wv = (const float*)d_in[5];
    const float* bv = (const float*)d_in[6];
    const float* Wo = (const float*)d_in[7];
    const float* bo = (const float*)d_in[8];
    float* out = (float*)d_out;

    k_init_freq<<<1, 512>>>();
    k_pe_transpose<<<dim3(SEQ / 32, DMODEL / 32, BATCH), dim3(32, 8)>>>(x);
    dim3 ggrid(DMODEL / 128, NTOK / 128);
    k_gemm_qkv<<<ggrid, 256>>>(Wq, bq, 0);
    k_gemm_qkv<<<ggrid, 256>>>(Wk, bk, 1);
    k_gemm_qkv<<<ggrid, 256>>>(Wv, bv, 2);
    k_flash<<<dim3(SEQ / 64, BATCH * NHEAD), 256>>>();
    k_gemm_out<<<ggrid, 256>>>(Wo, bo, out);
}